// round 13
// baseline (speedup 1.0000x reference)
#include <cuda_runtime.h>
#include <cuda_fp16.h>
#include <cstdint>

#define BATCH 8192
#define NNODE 30
#define FEAT  256
#define MROWS (BATCH * NNODE)   // 245760
#define NTILES (MROWS / 64)     // 3840
#define PGRID 148

// ---------------- scratch (device globals) ----------------
__device__ float  g_adj[(size_t)BATCH * NNODE * NNODE];  // 29.5 MB
__device__ __half g_y1[(size_t)MROWS * FEAT];
__device__ __half g_h1[(size_t)MROWS * FEAT];
__device__ __half g_u2[(size_t)MROWS * FEAT];
__device__ __half g_w1[FEAT * FEAT], g_w2[FEAT * FEAT];

// ==================== helpers ====================
__device__ __forceinline__ uint32_t smem_to_u32(const void* p) {
    uint32_t a;
    asm("{ .reg .u64 t; cvta.to.shared.u64 t, %1; cvt.u32.u64 %0, t; }" : "=r"(a) : "l"(p));
    return a;
}
__device__ __forceinline__ void cpasync16(uint32_t saddr, const void* g) {
    asm volatile("cp.async.cg.shared.global [%0], [%1], 16;" :: "r"(saddr), "l"(g));
}
__device__ __forceinline__ void ldsm4(uint32_t* r, uint32_t addr) {
    asm volatile("ldmatrix.sync.aligned.m8n8.x4.shared.b16 {%0,%1,%2,%3}, [%4];"
        : "=r"(r[0]), "=r"(r[1]), "=r"(r[2]), "=r"(r[3]) : "r"(addr));
}
__device__ __forceinline__ void mma_f16(float* d, const uint32_t* a, uint32_t b0, uint32_t b1) {
    asm volatile(
        "mma.sync.aligned.m16n8k16.row.col.f32.f16.f16.f32 "
        "{%0,%1,%2,%3}, {%4,%5,%6,%7}, {%8,%9}, {%0,%1,%2,%3};"
        : "+f"(d[0]), "+f"(d[1]), "+f"(d[2]), "+f"(d[3])
        : "r"(a[0]), "r"(a[1]), "r"(a[2]), "r"(a[3]), "r"(b0), "r"(b1));
}

// =====================================================================
// prep_w: transpose W1/W2 to [N,K] K-major fp16
// =====================================================================
__global__ void prep_w(const float* __restrict__ W1, const float* __restrict__ W2,
                       __half* __restrict__ w1, __half* __restrict__ w2) {
    const int n = blockIdx.x, k = threadIdx.x;
    w1[n * 256 + k] = __float2half_rn(W1[k * 256 + n]);
    w2[n * 256 + k] = __float2half_rn(W2[k * 256 + n]);
}

// =====================================================================
// Shared small-GEMM addressing (M=32/K=32 A; N=256/K=32 B):
//  A layout: per batch 2KB: phys row r(0..15)=128B holds m=r (bytes 0..63)
//    and m=r+16 (64..127); k-byte kb in [0,64) swizzled kb^((r&3)<<4).
//  B layout: per batch 16KB: phys row r(0..127)=128B holds n=r and n=r+128;
//    same 64B-half swizzle by (n&3).
// =====================================================================

// ---------------------------------------------------------------------
// k_prep2: adj = mean(graph); y1 = adj @ x  (tensor, 3-pass hi/lo split)
// 4 batches / 512-thread CTA. adj also stored fp32 to gmem.
// smem: XH[0,64K) XL[64K,128K) AH[128K,+8K) AL[+8K)
// ---------------------------------------------------------------------
#define KP_XH 0u
#define KP_XL 65536u
#define KP_AH 131072u
#define KP_AL 139264u
#define KP_TOTAL 147456

__global__ __launch_bounds__(512, 1)
void k_prep2(const float* __restrict__ graph, const float* __restrict__ x,
             float* __restrict__ adj_out, __half* __restrict__ y1) {
    extern __shared__ char smem[];
    const uint32_t sb = smem_to_u32(smem);
    const int tid = threadIdx.x, lane = tid & 31, wid = tid >> 5;
    const size_t gb0 = (size_t)blockIdx.x * 4;

    // zero A regions (16KB)
    #pragma unroll
    for (int u = tid; u < 1024; u += 512)
        *(uint4*)(smem + KP_AH + u * 16) = make_uint4(0, 0, 0, 0);
    __syncthreads();

    // ---- adj = mean(graph); store fp32; split hi/lo into A layout ----
    #pragma unroll 1
    for (int e = tid; e < 3600; e += 512) {
        int b = e / 900, idx = e - b * 900;
        int i = idx / 30, k = idx - i * 30;
        const float* gp = graph + (gb0 + b) * 4500 + idx;
        float s = 0.2f * (gp[0] + gp[900] + gp[1800] + gp[2700] + gp[3600]);
        adj_out[(gb0 + b) * 900 + idx] = s;
        __half h = __float2half_rn(s);
        float l = s - __half2float(h);
        uint32_t off = (uint32_t)b * 2048u + (uint32_t)((i & 15) * 128 + (i >> 4) * 64)
                     + (((uint32_t)(k * 2)) ^ ((uint32_t)(i & 3) << 4));
        *(__half*)(smem + KP_AH + off) = h;
        *(__half*)(smem + KP_AL + off) = __float2half_rn(l);
    }

    // ---- x -> transposed fp16 hi/lo B layout ----
    {
        const int b = tid >> 7, t2 = tid & 127;
        const int col0 = t2 * 2;
        #pragma unroll 1
        for (int k = 0; k < 30; ++k) {
            float2 v = *(const float2*)(x + ((gb0 + b) * 30 + k) * 256 + col0);
            #pragma unroll
            for (int cc = 0; cc < 2; ++cc) {
                int col = col0 + cc;
                float vv = cc ? v.y : v.x;
                __half h = __float2half_rn(vv);
                float l = vv - __half2float(h);
                uint32_t off = (uint32_t)b * 16384u
                             + (uint32_t)((col & 127) * 128 + (col >> 7) * 64)
                             + (((uint32_t)(k * 2)) ^ ((uint32_t)(col & 3) << 4));
                *(__half*)(smem + KP_XH + off) = h;
                *(__half*)(smem + KP_XL + off) = __float2half_rn(l);
            }
        }
        // zero k-pad (k=30,31) — 4B per col
        #pragma unroll
        for (int cc = 0; cc < 2; ++cc) {
            int col = col0 + cc;
            uint32_t off = (uint32_t)b * 16384u
                         + (uint32_t)((col & 127) * 128 + (col >> 7) * 64)
                         + (60u ^ ((uint32_t)(col & 3) << 4));
            *(uint32_t*)(smem + KP_XH + off) = 0u;
            *(uint32_t*)(smem + KP_XL + off) = 0u;
        }
    }
    __syncthreads();

    // ---- HMMA: warp w -> batch w>>2, n-slice (w&3)*64 ----
    const int batch = wid >> 2, wn = wid & 3;
    const int matv = lane >> 3;
    const int rA = (matv & 1) * 8 + (lane & 7);
    const int kAoff = (matv >> 1) * 16;
    const int nB0 = wn * 64 + matv * 8 + (lane & 7);
    const uint32_t abase = sb + (uint32_t)batch * 2048u + (uint32_t)(rA * 128);
    const uint32_t aswz = ((uint32_t)(rA & 3)) << 4;
    const uint32_t bswz = ((uint32_t)(nB0 & 3)) << 4;

    float acc[2][8][4];
    #pragma unroll
    for (int m = 0; m < 2; ++m)
        #pragma unroll
        for (int j = 0; j < 8; ++j)
            #pragma unroll
            for (int q = 0; q < 4; ++q) acc[m][j][q] = 0.f;

    #pragma unroll
    for (int pass = 0; pass < 3; ++pass) {
        const uint32_t aarr = (pass == 2) ? KP_AL : KP_AH;
        const uint32_t barr = (pass == 1) ? KP_XL : KP_XH;
        const uint32_t bb = sb + barr + (uint32_t)batch * 16384u;
        #pragma unroll
        for (int ks = 0; ks < 2; ++ks) {
            uint32_t a_f[2][4];
            #pragma unroll
            for (int mt = 0; mt < 2; ++mt)
                ldsm4(a_f[mt], abase + aarr + (uint32_t)(mt * 64)
                      + (((uint32_t)(ks * 32 + kAoff)) ^ aswz));
            uint32_t b0[2][4], b1[2][4];
            #pragma unroll
            for (int jb = 0; jb < 2; ++jb) {
                int n = nB0 + jb * 32;
                uint32_t ro = (uint32_t)((n & 127) * 128 + (n >> 7) * 64);
                ldsm4(b0[jb], bb + ro + (((uint32_t)(ks * 32)) ^ bswz));
                ldsm4(b1[jb], bb + ro + (((uint32_t)(ks * 32 + 16)) ^ bswz));
            }
            #pragma unroll
            for (int mt = 0; mt < 2; ++mt)
                #pragma unroll
                for (int jb = 0; jb < 2; ++jb)
                    #pragma unroll
                    for (int jj = 0; jj < 4; ++jj)
                        mma_f16(acc[mt][jb * 4 + jj], a_f[mt], b0[jb][jj], b1[jb][jj]);
        }
    }

    // ---- write y1 fp16 ----
    const int g = lane >> 2, cq = (lane & 3) * 2;
    #pragma unroll
    for (int mt = 0; mt < 2; ++mt) {
        int row0 = mt * 16 + g, row1 = row0 + 8;
        size_t rb = ((gb0 + batch) * 30) * 256;
        #pragma unroll
        for (int j = 0; j < 8; ++j) {
            int col = wn * 64 + j * 8 + cq;
            *(__half2*)(y1 + rb + (size_t)row0 * 256 + col) =
                __floats2half2_rn(acc[mt][j][0], acc[mt][j][1]);
            if (row1 < 30)
                *(__half2*)(y1 + rb + (size_t)row1 * 256 + col) =
                    __floats2half2_rn(acc[mt][j][2], acc[mt][j][3]);
        }
    }
}

// ---------------------------------------------------------------------
// k_final2: g2 = adj @ u2 (tensor, 2-pass adj hi/lo); fused tail:
// p = relu(g2+b2).wlin ; xl = relu(p+blin) ; out = xl @ Whead^T + bhead
// smem: UH[0,64K) AH[64K,+8K) AL[+8K) B2S WLS RED XLS
// ---------------------------------------------------------------------
#define KF_UH  0u
#define KF_AH  65536u
#define KF_AL  73728u
#define KF_B2  81920u
#define KF_WL  82944u
#define KF_RED 83968u
#define KF_XL  86016u
#define KF_TOTAL 86528

__global__ __launch_bounds__(512, 1)
void k_final2(const float* __restrict__ adj, const __half* __restrict__ u2,
              const float* __restrict__ b2g, const float* __restrict__ wling,
              const float* __restrict__ bling, const float* __restrict__ Wheadg,
              const float* __restrict__ bheadg, float* __restrict__ out) {
    extern __shared__ char smem[];
    const uint32_t sb = smem_to_u32(smem);
    const int tid = threadIdx.x, lane = tid & 31, wid = tid >> 5;
    const size_t gb0 = (size_t)blockIdx.x * 4;
    float* red = (float*)(smem + KF_RED);

    #pragma unroll
    for (int u = tid; u < 1024; u += 512)
        *(uint4*)(smem + KF_AH + u * 16) = make_uint4(0, 0, 0, 0);
    if (tid < 256) {
        ((float*)(smem + KF_B2))[tid] = b2g[tid];
        ((float*)(smem + KF_WL))[tid] = wling[tid];
    }
    __syncthreads();

    // ---- adj load + split ----
    #pragma unroll 1
    for (int e = tid; e < 3600; e += 512) {
        int b = e / 900, idx = e - b * 900;
        int i = idx / 30, k = idx - i * 30;
        float s = adj[(gb0 + b) * 900 + idx];
        __half h = __float2half_rn(s);
        float l = s - __half2float(h);
        uint32_t off = (uint32_t)b * 2048u + (uint32_t)((i & 15) * 128 + (i >> 4) * 64)
                     + (((uint32_t)(k * 2)) ^ ((uint32_t)(i & 3) << 4));
        *(__half*)(smem + KF_AH + off) = h;
        *(__half*)(smem + KF_AL + off) = __float2half_rn(l);
    }

    // ---- u2 -> transposed B layout (fp16, no split) ----
    {
        const int b = tid >> 7, t2 = tid & 127;
        const int col0 = t2 * 2;
        #pragma unroll 1
        for (int k = 0; k < 30; ++k) {
            __half2 v = *(const __half2*)(u2 + ((gb0 + b) * 30 + k) * 256 + col0);
            #pragma unroll
            for (int cc = 0; cc < 2; ++cc) {
                int col = col0 + cc;
                uint32_t off = (uint32_t)b * 16384u
                             + (uint32_t)((col & 127) * 128 + (col >> 7) * 64)
                             + (((uint32_t)(k * 2)) ^ ((uint32_t)(col & 3) << 4));
                *(__half*)(smem + KF_UH + off) = cc ? __high2half(v) : __low2half(v);
            }
        }
        #pragma unroll
        for (int cc = 0; cc < 2; ++cc) {
            int col = col0 + cc;
            uint32_t off = (uint32_t)b * 16384u
                         + (uint32_t)((col & 127) * 128 + (col >> 7) * 64)
                         + (60u ^ ((uint32_t)(col & 3) << 4));
            *(uint32_t*)(smem + KF_UH + off) = 0u;
        }
    }
    __syncthreads();

    // ---- HMMA 2 passes ----
    const int batch = wid >> 2, wn = wid & 3;
    const int matv = lane >> 3;
    const int rA = (matv & 1) * 8 + (lane & 7);
    const int kAoff = (matv >> 1) * 16;
    const int nB0 = wn * 64 + matv * 8 + (lane & 7);
    const uint32_t abase = sb + (uint32_t)batch * 2048u + (uint32_t)(rA * 128);
    const uint32_t aswz = ((uint32_t)(rA & 3)) << 4;
    const uint32_t bswz = ((uint32_t)(nB0 & 3)) << 4;
    const uint32_t bb = sb + KF_UH + (uint32_t)batch * 16384u;

    float acc[2][8][4];
    #pragma unroll
    for (int m = 0; m < 2; ++m)
        #pragma unroll
        for (int j = 0; j < 8; ++j)
            #pragma unroll
            for (int q = 0; q < 4; ++q) acc[m][j][q] = 0.f;

    #pragma unroll
    for (int pass = 0; pass < 2; ++pass) {
        const uint32_t aarr = pass ? KF_AL : KF_AH;
        #pragma unroll
        for (int ks = 0; ks < 2; ++ks) {
            uint32_t a_f[2][4];
            #pragma unroll
            for (int mt = 0; mt < 2; ++mt)
                ldsm4(a_f[mt], abase + aarr + (uint32_t)(mt * 64)
                      + (((uint32_t)(ks * 32 + kAoff)) ^ aswz));
            uint32_t b0[2][4], b1[2][4];
            #pragma unroll
            for (int jb = 0; jb < 2; ++jb) {
                int n = nB0 + jb * 32;
                uint32_t ro = (uint32_t)((n & 127) * 128 + (n >> 7) * 64);
                ldsm4(b0[jb], bb + ro + (((uint32_t)(ks * 32)) ^ bswz));
                ldsm4(b1[jb], bb + ro + (((uint32_t)(ks * 32 + 16)) ^ bswz));
            }
            #pragma unroll
            for (int mt = 0; mt < 2; ++mt)
                #pragma unroll
                for (int jb = 0; jb < 2; ++jb)
                    #pragma unroll
                    for (int jj = 0; jj < 4; ++jj)
                        mma_f16(acc[mt][jb * 4 + jj], a_f[mt], b0[jb][jj], b1[jb][jj]);
        }
    }

    // ---- fused tail: per-row dot with wlin after relu(+b2) ----
    const int g = lane >> 2, cq = (lane & 3) * 2;
    const float* b2s = (const float*)(smem + KF_B2);
    const float* wls = (const float*)(smem + KF_WL);
    float pr[4] = {0.f, 0.f, 0.f, 0.f};
    #pragma unroll
    for (int mt = 0; mt < 2; ++mt)
        #pragma unroll
        for (int j = 0; j < 8; ++j) {
            int col = wn * 64 + j * 8 + cq;
            float bb0 = b2s[col], bb1 = b2s[col + 1];
            float w0 = wls[col], w1 = wls[col + 1];
            pr[mt * 2]     += fmaxf(acc[mt][j][0] + bb0, 0.f) * w0
                            + fmaxf(acc[mt][j][1] + bb1, 0.f) * w1;
            pr[mt * 2 + 1] += fmaxf(acc[mt][j][2] + bb0, 0.f) * w0
                            + fmaxf(acc[mt][j][3] + bb1, 0.f) * w1;
        }
    #pragma unroll
    for (int r4 = 0; r4 < 4; ++r4) {
        float v = pr[r4];
        v += __shfl_xor_sync(0xffffffffu, v, 1);
        v += __shfl_xor_sync(0xffffffffu, v, 2);
        pr[r4] = v;
    }
    if ((lane & 3) == 0) {
        #pragma unroll
        for (int r4 = 0; r4 < 4; ++r4) {
            int row = (r4 >> 1) * 16 + (r4 & 1) * 8 + g;
            red[(batch * 32 + row) * 4 + wn] = pr[r4];
        }
    }
    __syncthreads();

    float* xls = (float*)(smem + KF_XL);
    if (tid < 120) {
        int b = tid / 30, i = tid - b * 30;
        const float* rp = red + (b * 32 + i) * 4;
        xls[b * 32 + i] = fmaxf(rp[0] + rp[1] + rp[2] + rp[3] + __ldg(bling), 0.f);
    }
    __syncthreads();
    if (tid < 36) {
        int b = tid / 9, c = tid - b * 9;
        float s = __ldg(bheadg + c);
        #pragma unroll
        for (int i = 0; i < 30; ++i)
            s = fmaf(xls[b * 32 + i], __ldg(Wheadg + c * 30 + i), s);
        out[(gb0 + b) * 9 + c] = s;
    }
}

// =====================================================================
// Persistent GEMM (R10 best): W resident, 512 thr, warp tile 32x32.
// MODE 1: Out = relu(C+bias) -> fp16 ;  MODE 2: Out = C -> fp16
// =====================================================================
#define PSM_W    0u
#define PSM_A    131072u
#define PSM_BIAS 196608u
#define PSM_TOTAL 197632

template <int MODE>
__global__ __launch_bounds__(512, 1)
void gemm_persist(const __half* __restrict__ A, const __half* __restrict__ W,
                  const float* __restrict__ bias, __half* __restrict__ Out) {
    extern __shared__ char smem[];
    const uint32_t sb = smem_to_u32(smem);
    const int tid = threadIdx.x, lane = tid & 31, wid = tid >> 5;
    const int warp_m = wid & 1, warp_n = wid >> 1;

    #pragma unroll
    for (int u = tid; u < 8192; u += 512) {
        int kc = u >> 9, v = u & 511;
        int n = v >> 1, half = v & 1;
        int row = n & 63, sub = n >> 6;
        uint32_t off = (uint32_t)kc * 8192u + (uint32_t)(row * 128)
                     + (((uint32_t)(sub * 32 + half * 16)) ^ ((uint32_t)(row & 7) << 4));
        cpasync16(sb + PSM_W + off, W + (size_t)n * 256 + (size_t)kc * 16 + half * 8);
    }
    asm volatile("cp.async.commit_group;" ::: "memory");
    if (MODE == 1 && tid < 256) ((float*)(smem + PSM_BIAS))[tid] = bias[tid];

    auto aload = [&](int tile, int stage) {
        const __half* gA = A + (size_t)tile * 64 * 256;
        uint32_t st = sb + PSM_A + (uint32_t)stage * 32768u;
        #pragma unroll
        for (int u = tid; u < 2048; u += 512) {
            int row = u >> 5, s = u & 31;
            int c = s >> 3, ss = s & 7;
            uint32_t off = (uint32_t)c * 8192u + (uint32_t)(row * 128)
                         + (((uint32_t)ss * 16u) ^ ((uint32_t)(row & 7) << 4));
            cpasync16(st + off, gA + (size_t)row * 256 + s * 8);
        }
        asm volatile("cp.async.commit_group;" ::: "memory");
    };

    const int matv = lane >> 3;
    const int rA0 = warp_m * 32 + (matv & 1) * 8 + (lane & 7);
    const int kAoff = (matv >> 1) * 16;
    const int nB0 = warp_n * 32 + matv * 8 + (lane & 7);
    const uint32_t roB = (uint32_t)((nB0 & 63) * 128);
    const uint32_t baseB = (uint32_t)((nB0 >> 6) * 32);
    const uint32_t xorv = (uint32_t)((lane & 7) << 4);
    const int g = lane >> 2, cq = (lane & 3) * 2;

    int tile = blockIdx.x;
    aload(tile, 0);
    int it = 0;

    #pragma unroll 1
    for (; tile < NTILES; tile += PGRID, ++it) {
        const int stage = it & 1;
        asm volatile("cp.async.wait_group 0;" ::: "memory");
        __syncthreads();
        if (tile + PGRID < NTILES) aload(tile + PGRID, stage ^ 1);

        const uint32_t ab = sb + PSM_A + (uint32_t)stage * 32768u;
        float acc[2][4][4];
        #pragma unroll
        for (int m = 0; m < 2; ++m)
            #pragma unroll
            for (int j = 0; j < 4; ++j)
                #pragma unroll
                for (int q = 0; q < 4; ++q) acc[m][j][q] = 0.f;

        #pragma unroll 4
        for (int kc = 0; kc < 16; ++kc) {
            const uint32_t abase = ab + (uint32_t)(kc >> 2) * 8192u;
            const uint32_t aco = ((uint32_t)((kc & 3) * 32 + kAoff)) ^ xorv;
            uint32_t a_f[2][4];
            #pragma unroll
            for (int mt = 0; mt < 2; ++mt)
                ldsm4(a_f[mt], abase + (uint32_t)((rA0 + mt * 16) * 128) + aco);

            const uint32_t wst = sb + PSM_W + (uint32_t)kc * 8192u;
            uint32_t b0[4], b1[4];
            ldsm4(b0, wst + roB + (baseB ^ xorv));
            ldsm4(b1, wst + roB + ((baseB + 16u) ^ xorv));
            #pragma unroll
            for (int mt = 0; mt < 2; ++mt)
                #pragma unroll
                for (int jj = 0; jj < 4; ++jj)
                    mma_f16(acc[mt][jj], a_f[mt], b0[jj], b1[jj]);
        }

        #pragma unroll
        for (int mt = 0; mt < 2; ++mt) {
            const size_t r0 = (size_t)tile * 64 + warp_m * 32 + mt * 16 + g;
            #pragma unroll
            for (int j = 0; j < 4; ++j) {
                const int col = warp_n * 32 + j * 8 + cq;
                if (MODE == 1) {
                    const float* bs = (const float*)(smem + PSM_BIAS);
                    float bb0 = bs[col], bb1 = bs[col + 1];
                    *(__half2*)(Out + r0 * 256 + col) = __floats2half2_rn(
                        fmaxf(acc[mt][j][0] + bb0, 0.f), fmaxf(acc[mt][j][1] + bb1, 0.f));
                    *(__half2*)(Out + (r0 + 8) * 256 + col) = __floats2half2_rn(
                        fmaxf(acc[mt][j][2] + bb0, 0.f), fmaxf(acc[mt][j][3] + bb1, 0.f));
                } else {
                    *(__half2*)(Out + r0 * 256 + col) =
                        __floats2half2_rn(acc[mt][j][0], acc[mt][j][1]);
                    *(__half2*)(Out + (r0 + 8) * 256 + col) =
                        __floats2half2_rn(acc[mt][j][2], acc[mt][j][3]);
                }
            }
        }
    }
}

// =====================================================================
extern "C" void kernel_launch(void* const* d_in, const int* in_sizes, int n_in,
                              void* d_out, int out_size) {
    const float* real  = (const float*)d_in[0];
    const float* graph = (const float*)d_in[2];
    const float* W1    = (const float*)d_in[3];
    const float* b1    = (const float*)d_in[4];
    const float* W2    = (const float*)d_in[5];
    const float* b2    = (const float*)d_in[6];
    const float* wlin  = (const float*)d_in[7];
    const float* blin  = (const float*)d_in[8];
    const float* Whead = (const float*)d_in[9];
    const float* bhead = (const float*)d_in[10];
    float* out = (float*)d_out;

    float *adj_p;
    __half *y1_p, *h1_p, *u2_p, *w1_p, *w2_p;
    cudaGetSymbolAddress((void**)&adj_p, g_adj);
    cudaGetSymbolAddress((void**)&y1_p,  g_y1);
    cudaGetSymbolAddress((void**)&h1_p,  g_h1);
    cudaGetSymbolAddress((void**)&u2_p,  g_u2);
    cudaGetSymbolAddress((void**)&w1_p,  g_w1);
    cudaGetSymbolAddress((void**)&w2_p,  g_w2);

    cudaFuncSetAttribute(gemm_persist<1>, cudaFuncAttributeMaxDynamicSharedMemorySize, PSM_TOTAL);
    cudaFuncSetAttribute(gemm_persist<2>, cudaFuncAttributeMaxDynamicSharedMemorySize, PSM_TOTAL);
    cudaFuncSetAttribute(k_prep2,  cudaFuncAttributeMaxDynamicSharedMemorySize, KP_TOTAL);
    cudaFuncSetAttribute(k_final2, cudaFuncAttributeMaxDynamicSharedMemorySize, KF_TOTAL);

    // 1. weight transpose to fp16 [N,K]
    prep_w<<<256, 256>>>(W1, W2, w1_p, w2_p);
    // 2. adj = mean(graph); y1 = adj @ real  (tensor, 3-pass split)
    k_prep2<<<BATCH / 4, 512, KP_TOTAL>>>(graph, real, adj_p, y1_p);
    // 3. h1 = relu(y1 @ W1 + b1)  (persistent, W1 resident)
    gemm_persist<1><<<PGRID, 512, PSM_TOTAL>>>(y1_p, w1_p, b1, h1_p);
    // 4. u2 = h1 @ W2             (persistent, W2 resident)
    gemm_persist<2><<<PGRID, 512, PSM_TOTAL>>>(h1_p, w2_p, nullptr, u2_p);
    // 5. g2 = adj @ u2 (tensor, 2-pass) + fused relu/wlin/head -> out
    k_final2<<<BATCH / 4, 512, KF_TOTAL>>>(adj_p, u2_p, b2, wlin, blin,
                                           Whead, bhead, out);
}

// round 14
// speedup vs baseline: 1.6740x; 1.6740x over previous
#include <cuda_runtime.h>
#include <cuda_fp16.h>
#include <cstdint>

#define BATCH 8192
#define NNODE 30
#define FEAT  256
#define MROWS (BATCH * NNODE)   // 245760
#define NTILES (MROWS / 64)     // 3840
#define PGRID 148

// ---------------- scratch (device globals) ----------------
__device__ float  g_adj[(size_t)BATCH * NNODE * NNODE];  // 29.5 MB
__device__ __half g_y1[(size_t)MROWS * FEAT];
__device__ __half g_h1[(size_t)MROWS * FEAT];
__device__ __half g_u2[(size_t)MROWS * FEAT];
__device__ __half g_w1[FEAT * FEAT], g_w2[FEAT * FEAT];

// ==================== helpers ====================
__device__ __forceinline__ uint32_t smem_to_u32(const void* p) {
    uint32_t a;
    asm("{ .reg .u64 t; cvta.to.shared.u64 t, %1; cvt.u32.u64 %0, t; }" : "=r"(a) : "l"(p));
    return a;
}
__device__ __forceinline__ void cpasync16(uint32_t saddr, const void* g) {
    asm volatile("cp.async.cg.shared.global [%0], [%1], 16;" :: "r"(saddr), "l"(g));
}
__device__ __forceinline__ void ldsm4(uint32_t* r, uint32_t addr) {
    asm volatile("ldmatrix.sync.aligned.m8n8.x4.shared.b16 {%0,%1,%2,%3}, [%4];"
        : "=r"(r[0]), "=r"(r[1]), "=r"(r[2]), "=r"(r[3]) : "r"(addr));
}
__device__ __forceinline__ void mma_f16(float* d, const uint32_t* a, uint32_t b0, uint32_t b1) {
    asm volatile(
        "mma.sync.aligned.m16n8k16.row.col.f32.f16.f16.f32 "
        "{%0,%1,%2,%3}, {%4,%5,%6,%7}, {%8,%9}, {%0,%1,%2,%3};"
        : "+f"(d[0]), "+f"(d[1]), "+f"(d[2]), "+f"(d[3])
        : "r"(a[0]), "r"(a[1]), "r"(a[2]), "r"(a[3]), "r"(b0), "r"(b1));
}
__device__ __forceinline__ unsigned long long pk2(float x, float y) {
    unsigned long long r;
    asm("mov.b64 %0, {%1, %2};" : "=l"(r) : "f"(x), "f"(y));
    return r;
}
__device__ __forceinline__ void upk2(unsigned long long v, float& x, float& y) {
    asm("mov.b64 {%0, %1}, %2;" : "=f"(x), "=f"(y) : "l"(v));
}
__device__ __forceinline__ unsigned long long fma2(unsigned long long a,
                                                   unsigned long long b,
                                                   unsigned long long c) {
    unsigned long long d;
    asm("fma.rn.f32x2 %0, %1, %2, %3;" : "=l"(d) : "l"(a), "l"(b), "l"(c));
    return d;
}

// =====================================================================
// prep_w: transpose W1/W2 to [N,K] K-major fp16
// =====================================================================
__global__ void prep_w(const float* __restrict__ W1, const float* __restrict__ W2,
                       __half* __restrict__ w1, __half* __restrict__ w2) {
    const int n = blockIdx.x, k = threadIdx.x;
    w1[n * 256 + k] = __float2half_rn(W1[k * 256 + n]);
    w2[n * 256 + k] = __float2half_rn(W2[k * 256 + n]);
}

// =====================================================================
// k_prep: adj = mean(graph, bands); y1 = adj @ x -> fp16
// adj rows padded to 32 floats; inner loop uses LDS.128 (4 adj/load).
// =====================================================================
__global__ __launch_bounds__(128)
void k_prep(const float* __restrict__ graph, const float* __restrict__ x,
            float* __restrict__ adj_out, __half* __restrict__ y1) {
    __shared__ __align__(16) float adj_s[960];
    const int tid = threadIdx.x;
    const size_t b = blockIdx.x;

    const float* gp = graph + b * 4500;
    float* ao = adj_out + b * 900;
    for (int e = tid; e < 900; e += 128) {
        int i = e / 30, k = e - i * 30;
        float s = 0.2f * (gp[e] + gp[e + 900] + gp[e + 1800] + gp[e + 2700] + gp[e + 3600]);
        adj_s[i * 32 + k] = s;
        ao[e] = s;
    }
    if (tid < 60) adj_s[(tid >> 1) * 32 + 30 + (tid & 1)] = 0.f;

    const int j = tid * 2;
    const float* xp = x + b * 7680 + j;
    unsigned long long xr[32];
    #pragma unroll
    for (int k = 0; k < 30; ++k) {
        float2 v = *(const float2*)(xp + (size_t)k * 256);
        xr[k] = pk2(v.x, v.y);
    }
    xr[30] = 0ULL; xr[31] = 0ULL;
    __syncthreads();

    #pragma unroll 1
    for (int i = 0; i < 30; ++i) {
        unsigned long long acc = 0ULL;
        const float* ar = adj_s + i * 32;
        #pragma unroll
        for (int k4 = 0; k4 < 8; ++k4) {
            float4 a4 = *(const float4*)(ar + k4 * 4);
            acc = fma2(pk2(a4.x, a4.x), xr[k4 * 4 + 0], acc);
            acc = fma2(pk2(a4.y, a4.y), xr[k4 * 4 + 1], acc);
            acc = fma2(pk2(a4.z, a4.z), xr[k4 * 4 + 2], acc);
            acc = fma2(pk2(a4.w, a4.w), xr[k4 * 4 + 3], acc);
        }
        float y0, yy;
        upk2(acc, y0, yy);
        *(__half2*)(y1 + (b * 30 + i) * 256 + j) = __floats2half2_rn(y0, yy);
    }
}

// =====================================================================
// Persistent GEMM (R10): W resident, 512 thr, 16 warps, warp tile 32x32.
// MODE 1: Out = relu(C+bias) -> fp16 ;  MODE 2: Out = C -> fp16
// =====================================================================
#define PSM_W    0u
#define PSM_A    131072u
#define PSM_BIAS 196608u
#define PSM_TOTAL 197632

template <int MODE>
__global__ __launch_bounds__(512, 1)
void gemm_persist(const __half* __restrict__ A, const __half* __restrict__ W,
                  const float* __restrict__ bias, __half* __restrict__ Out) {
    extern __shared__ char smem[];
    const uint32_t sb = smem_to_u32(smem);
    const int tid = threadIdx.x, lane = tid & 31, wid = tid >> 5;
    const int warp_m = wid & 1, warp_n = wid >> 1;

    #pragma unroll
    for (int u = tid; u < 8192; u += 512) {
        int kc = u >> 9, v = u & 511;
        int n = v >> 1, half = v & 1;
        int row = n & 63, sub = n >> 6;
        uint32_t off = (uint32_t)kc * 8192u + (uint32_t)(row * 128)
                     + (((uint32_t)(sub * 32 + half * 16)) ^ ((uint32_t)(row & 7) << 4));
        cpasync16(sb + PSM_W + off, W + (size_t)n * 256 + (size_t)kc * 16 + half * 8);
    }
    asm volatile("cp.async.commit_group;" ::: "memory");
    if (MODE == 1 && tid < 256) ((float*)(smem + PSM_BIAS))[tid] = bias[tid];

    auto aload = [&](int tile, int stage) {
        const __half* gA = A + (size_t)tile * 64 * 256;
        uint32_t st = sb + PSM_A + (uint32_t)stage * 32768u;
        #pragma unroll
        for (int u = tid; u < 2048; u += 512) {
            int row = u >> 5, s = u & 31;
            int c = s >> 3, ss = s & 7;
            uint32_t off = (uint32_t)c * 8192u + (uint32_t)(row * 128)
                         + (((uint32_t)ss * 16u) ^ ((uint32_t)(row & 7) << 4));
            cpasync16(st + off, gA + (size_t)row * 256 + s * 8);
        }
        asm volatile("cp.async.commit_group;" ::: "memory");
    };

    const int matv = lane >> 3;
    const int rA0 = warp_m * 32 + (matv & 1) * 8 + (lane & 7);
    const int kAoff = (matv >> 1) * 16;
    const int nB0 = warp_n * 32 + matv * 8 + (lane & 7);
    const uint32_t roB = (uint32_t)((nB0 & 63) * 128);
    const uint32_t baseB = (uint32_t)((nB0 >> 6) * 32);
    const uint32_t xorv = (uint32_t)((lane & 7) << 4);
    const int g = lane >> 2, cq = (lane & 3) * 2;

    int tile = blockIdx.x;
    aload(tile, 0);
    int it = 0;

    #pragma unroll 1
    for (; tile < NTILES; tile += PGRID, ++it) {
        const int stage = it & 1;
        asm volatile("cp.async.wait_group 0;" ::: "memory");
        __syncthreads();
        if (tile + PGRID < NTILES) aload(tile + PGRID, stage ^ 1);

        const uint32_t ab = sb + PSM_A + (uint32_t)stage * 32768u;
        float acc[2][4][4];
        #pragma unroll
        for (int m = 0; m < 2; ++m)
            #pragma unroll
            for (int j = 0; j < 4; ++j)
                #pragma unroll
                for (int q = 0; q < 4; ++q) acc[m][j][q] = 0.f;

        #pragma unroll 4
        for (int kc = 0; kc < 16; ++kc) {
            const uint32_t abase = ab + (uint32_t)(kc >> 2) * 8192u;
            const uint32_t aco = ((uint32_t)((kc & 3) * 32 + kAoff)) ^ xorv;
            uint32_t a_f[2][4];
            #pragma unroll
            for (int mt = 0; mt < 2; ++mt)
                ldsm4(a_f[mt], abase + (uint32_t)((rA0 + mt * 16) * 128) + aco);

            const uint32_t wst = sb + PSM_W + (uint32_t)kc * 8192u;
            uint32_t b0[4], b1[4];
            ldsm4(b0, wst + roB + (baseB ^ xorv));
            ldsm4(b1, wst + roB + ((baseB + 16u) ^ xorv));
            #pragma unroll
            for (int mt = 0; mt < 2; ++mt)
                #pragma unroll
                for (int jj = 0; jj < 4; ++jj)
                    mma_f16(acc[mt][jj], a_f[mt], b0[jj], b1[jj]);
        }

        #pragma unroll
        for (int mt = 0; mt < 2; ++mt) {
            const size_t r0 = (size_t)tile * 64 + warp_m * 32 + mt * 16 + g;
            #pragma unroll
            for (int j = 0; j < 4; ++j) {
                const int col = warp_n * 32 + j * 8 + cq;
                if (MODE == 1) {
                    const float* bs = (const float*)(smem + PSM_BIAS);
                    float bb0 = bs[col], bb1 = bs[col + 1];
                    *(__half2*)(Out + r0 * 256 + col) = __floats2half2_rn(
                        fmaxf(acc[mt][j][0] + bb0, 0.f), fmaxf(acc[mt][j][1] + bb1, 0.f));
                    *(__half2*)(Out + (r0 + 8) * 256 + col) = __floats2half2_rn(
                        fmaxf(acc[mt][j][2] + bb0, 0.f), fmaxf(acc[mt][j][3] + bb1, 0.f));
                } else {
                    *(__half2*)(Out + r0 * 256 + col) =
                        __floats2half2_rn(acc[mt][j][0], acc[mt][j][1]);
                    *(__half2*)(Out + (r0 + 8) * 256 + col) =
                        __floats2half2_rn(acc[mt][j][2], acc[mt][j][3]);
                }
            }
        }
    }
}

// =====================================================================
// k_final: g2 = adj @ u2; p = relu(g2+b2).wlin; xl = relu(p+blin);
//          out = xl @ W_head^T + b_head.  u2 fp16; LDS.128 adj loads.
// =====================================================================
__global__ __launch_bounds__(512)
void k_final(const float* __restrict__ adj, const __half* __restrict__ u2,
             const float* __restrict__ b2g, const float* __restrict__ wling,
             const float* __restrict__ bling, const float* __restrict__ Wheadg,
             const float* __restrict__ bheadg, float* __restrict__ out) {
    __shared__ __align__(16) float adj_s[4 * 960];
    __shared__ float red[4][30][4];
    const int tid = threadIdx.x;
    const int b = tid >> 7, t2 = tid & 127, w = t2 >> 5;
    const size_t b0 = (size_t)blockIdx.x * 4;

    for (int e = tid; e < 3600; e += 512) {
        int bb = e / 900, i = e - bb * 900;
        adj_s[bb * 960 + (i / 30) * 32 + (i % 30)] = adj[(b0 + bb) * 900 + i];
    }
    if (tid < 240) {
        int bb = tid / 60, r = (tid % 60) >> 1;
        adj_s[bb * 960 + r * 32 + 30 + (tid & 1)] = 0.f;
    }

    const int j = t2 * 2;
    const __half* up = u2 + (b0 + b) * 7680 + j;
    unsigned long long uk[32];
    #pragma unroll
    for (int k = 0; k < 30; ++k) {
        float2 v = __half22float2(*(const __half2*)(up + (size_t)k * 256));
        uk[k] = pk2(v.x, v.y);
    }
    uk[30] = 0ULL; uk[31] = 0ULL;
    const float b2v0 = __ldg(b2g + j), b2v1 = __ldg(b2g + j + 1);
    const float wl0 = __ldg(wling + j), wl1 = __ldg(wling + j + 1);
    __syncthreads();

    const float* ar = adj_s + b * 960;
    #pragma unroll 1
    for (int i = 0; i < 30; ++i) {
        unsigned long long acc = 0ULL;
        const float* arow = ar + i * 32;
        #pragma unroll
        for (int k4 = 0; k4 < 8; ++k4) {
            float4 a4 = *(const float4*)(arow + k4 * 4);
            acc = fma2(pk2(a4.x, a4.x), uk[k4 * 4 + 0], acc);
            acc = fma2(pk2(a4.y, a4.y), uk[k4 * 4 + 1], acc);
            acc = fma2(pk2(a4.z, a4.z), uk[k4 * 4 + 2], acc);
            acc = fma2(pk2(a4.w, a4.w), uk[k4 * 4 + 3], acc);
        }
        float s0, s1;
        upk2(acc, s0, s1);
        float p = fmaxf(s0 + b2v0, 0.f) * wl0 + fmaxf(s1 + b2v1, 0.f) * wl1;
        #pragma unroll
        for (int o = 16; o > 0; o >>= 1) p += __shfl_xor_sync(0xffffffffu, p, o);
        if ((t2 & 31) == 0) red[b][i][w] = p;
    }
    __syncthreads();

    if (tid < 36) {
        const int bb = tid / 9, c = tid - bb * 9;
        const float bl = __ldg(bling);
        float s = __ldg(bheadg + c);
        #pragma unroll
        for (int i = 0; i < 30; ++i) {
            float xl = fmaxf(red[bb][i][0] + red[bb][i][1] + red[bb][i][2] + red[bb][i][3] + bl, 0.f);
            s = fmaf(xl, __ldg(Wheadg + c * 30 + i), s);
        }
        out[(b0 + bb) * 9 + c] = s;
    }
}

// =====================================================================
extern "C" void kernel_launch(void* const* d_in, const int* in_sizes, int n_in,
                              void* d_out, int out_size) {
    const float* real  = (const float*)d_in[0];
    const float* graph = (const float*)d_in[2];
    const float* W1    = (const float*)d_in[3];
    const float* b1    = (const float*)d_in[4];
    const float* W2    = (const float*)d_in[5];
    const float* b2    = (const float*)d_in[6];
    const float* wlin  = (const float*)d_in[7];
    const float* blin  = (const float*)d_in[8];
    const float* Whead = (const float*)d_in[9];
    const float* bhead = (const float*)d_in[10];
    float* out = (float*)d_out;

    float *adj_p;
    __half *y1_p, *h1_p, *u2_p, *w1_p, *w2_p;
    cudaGetSymbolAddress((void**)&adj_p, g_adj);
    cudaGetSymbolAddress((void**)&y1_p,  g_y1);
    cudaGetSymbolAddress((void**)&h1_p,  g_h1);
    cudaGetSymbolAddress((void**)&u2_p,  g_u2);
    cudaGetSymbolAddress((void**)&w1_p,  g_w1);
    cudaGetSymbolAddress((void**)&w2_p,  g_w2);

    cudaFuncSetAttribute(gemm_persist<1>, cudaFuncAttributeMaxDynamicSharedMemorySize, PSM_TOTAL);
    cudaFuncSetAttribute(gemm_persist<2>, cudaFuncAttributeMaxDynamicSharedMemorySize, PSM_TOTAL);

    // 1. weight transpose to fp16 [N,K]
    prep_w<<<256, 256>>>(W1, W2, w1_p, w2_p);
    // 2. adj = mean(graph); y1 = adj @ real (fp16)
    k_prep<<<BATCH, 128>>>(graph, real, adj_p, y1_p);
    // 3. h1 = relu(y1 @ W1 + b1)  (persistent, W1 resident)
    gemm_persist<1><<<PGRID, 512, PSM_TOTAL>>>(y1_p, w1_p, b1, h1_p);
    // 4. u2 = h1 @ W2             (persistent, W2 resident)
    gemm_persist<2><<<PGRID, 512, PSM_TOTAL>>>(h1_p, w2_p, nullptr, u2_p);
    // 5. fused: g2 = adj@u2; relu(+b2).wlin; relu(+blin); head -> out
    k_final<<<BATCH / 4, 512>>>(adj_p, u2_p, b2, wlin, blin, Whead, bhead, out);
}